// round 3
// baseline (speedup 1.0000x reference)
#include <cuda_runtime.h>

// Problem geometry (fixed by the dataset):
//   y: [1,512,512,8,8] f32 = 16,777,216 elems
//   c: [2,256,256,8,8] f32 =  8,388,608 elems (2 channels x 4,194,304)
// Output: y then c concatenated, 25,165,824 f32.
//
// Single fused launch:
//   blocks [0, 512)        : extra duty — DC reduction (clamped c[idx*64]),
//                            atomicAdd into g_dc_sum, bump g_red_cnt. Then
//                            their normal y elementwise work.
//   blocks [0, 16384)      : y elementwise (float4)
//   blocks [16384, 24576)  : c elementwise; spin (one check in practice —
//                            these run ~13 waves after the reducers finish)
//                            on g_red_cnt == 512, then apply DC mean blend.
//   last c-block resets all globals so the graph replay starts clean.

#define CMIN  (-1024.0f)
#define CMAX  (1016.0f)
#define FACT  (1.9f)

static const long long NY4       = 4194304LL;   // y float4 count
static const long long NC4       = 2097152LL;   // c float4 count
static const int       N_RED_BLK = 512;         // reducer blocks (256 DC each)
static const int       N_C_BLK   = 8192;        // c blocks
static const float     INV_CNT   = 1.0f / 65536.0f;

__device__ float g_dc_sum[2];
__device__ int   g_red_cnt;
__device__ int   g_c_done;

__device__ __forceinline__ float clampf(float v) {
    return fminf(fmaxf(v, CMIN), CMAX);
}

__global__ void __launch_bounds__(256) fused_kernel(
    const float4* __restrict__ y, const float4* __restrict__ c,
    float4* __restrict__ oy, float4* __restrict__ oc)
{
    __shared__ float s_warp[8];

    // ---- Extra duty: DC reduction on first 512 blocks (wave 1) ----
    if (blockIdx.x < N_RED_BLK) {
        int idx = blockIdx.x * 256 + threadIdx.x;            // 0 .. 131071
        int ch  = idx >> 16;                                 // constant per block
        // DC coeff idx lives at c-element idx*64 == float4 idx*16, component .x
        float v = clampf(c[(long long)idx * 16].x);

        #pragma unroll
        for (int off = 16; off > 0; off >>= 1)
            v += __shfl_down_sync(0xffffffffu, v, off);
        if ((threadIdx.x & 31) == 0) s_warp[threadIdx.x >> 5] = v;
        __syncthreads();
        if (threadIdx.x < 8) {
            float w = s_warp[threadIdx.x];
            #pragma unroll
            for (int off = 4; off > 0; off >>= 1)
                w += __shfl_down_sync(0xffu, w, off);
            if (threadIdx.x == 0) {
                atomicAdd(&g_dc_sum[ch], w);
                __threadfence();
                atomicAdd(&g_red_cnt, 1);
            }
        }
        __syncthreads();   // s_warp reuse safety; also keeps block tight
    }

    long long i = (long long)blockIdx.x * 256 + threadIdx.x;

    if (i < NY4) {
        // ---- y elementwise ----
        float4 v = y[i];
        v.x = clampf(clampf(v.x) * FACT);
        v.y = clampf(clampf(v.y) * FACT);
        v.z = clampf(clampf(v.z) * FACT);
        v.w = clampf(clampf(v.w) * FACT);
        oy[i] = v;
    } else {
        // ---- c elementwise (+ DC mean blend) ----
        long long j = i - NY4;                    // 0 .. NC4-1
        int ch = (int)(j >> 20);                  // constant per block

        // Wait for reduction (completed ~13 waves earlier; effectively free).
        if (threadIdx.x == 0) {
            while (*((volatile int*)&g_red_cnt) != N_RED_BLK) { }
        }
        __syncthreads();
        float mean = (*((volatile float*)&g_dc_sum[ch])) * INV_CNT;

        float4 v = c[j];
        v.x = clampf(v.x) * FACT;
        v.y = clampf(v.y) * FACT;
        v.z = clampf(v.z) * FACT;
        v.w = clampf(v.w) * FACT;
        if ((j & 15) == 0)                        // elem j*4 is a DC coeff
            v.x += (1.0f - FACT) * mean;
        v.x = clampf(v.x);
        v.y = clampf(v.y);
        v.z = clampf(v.z);
        v.w = clampf(v.w);
        oc[j] = v;

        // ---- reset globals for next graph replay (last c-block) ----
        __syncthreads();
        if (threadIdx.x == 0) {
            int old = atomicAdd(&g_c_done, 1);
            if (old == N_C_BLK - 1) {
                *((volatile float*)&g_dc_sum[0]) = 0.0f;
                *((volatile float*)&g_dc_sum[1]) = 0.0f;
                *((volatile int*)&g_red_cnt)     = 0;
                *((volatile int*)&g_c_done)      = 0;
                __threadfence();
            }
        }
    }
}

extern "C" void kernel_launch(void* const* d_in, const int* in_sizes, int n_in,
                              void* d_out, int out_size) {
    const float4* y = (const float4*)d_in[0];
    const float4* c = (const float4*)d_in[1];
    float4* oy = (float4*)d_out;
    float4* oc = (float4*)((float*)d_out + NY4 * 4);

    unsigned grid = (unsigned)((NY4 + NC4) / 256);   // 24,576 blocks
    fused_kernel<<<grid, 256>>>(y, c, oy, oc);
}

// round 4
// speedup vs baseline: 1.3924x; 1.3924x over previous
#include <cuda_runtime.h>

// Problem geometry (fixed by the dataset):
//   y: [1,512,512,8,8] f32 = 16,777,216 elems
//   c: [2,256,256,8,8] f32 =  8,388,608 elems (2 channels x 4,194,304)
// Output: y then c concatenated, 25,165,824 f32.
//
// Single fused launch, 12,288 blocks x 256 threads, 2 float4 per thread
// (each block owns 512 consecutive float4s):
//   blocks [0, 512)        : extra duty — DC reduction (one clamped DC/thread),
//                            atomicAdd into g_dc_sum, bump g_red_cnt.
//   blocks [0, 8192)       : y elementwise (NY4/512 == 8192 exactly).
//   blocks [8192, 12288)   : c elementwise. Thread 0 polls g_red_cnt (done
//                            many waves earlier), reads the mean ONCE, and
//                            broadcasts via shared memory (no per-thread
//                            volatile loads of a single global address!).
//   Last c-block resets globals so graph replay starts clean.

#define CMIN  (-1024.0f)
#define CMAX  (1016.0f)
#define FACT  (1.9f)

static const long long NY4       = 4194304LL;   // y float4 count
static const long long NC4       = 2097152LL;   // c float4 count
static const int       N_RED_BLK = 512;         // reducer blocks (256 DC each)
static const int       N_C_BLK   = 4096;        // c blocks
static const float     INV_CNT   = 1.0f / 65536.0f;

__device__ float g_dc_sum[2];
__device__ int   g_red_cnt;
__device__ int   g_c_done;

__device__ __forceinline__ float clampf(float v) {
    return fminf(fmaxf(v, CMIN), CMAX);
}

__device__ __forceinline__ float4 y_op(float4 v) {
    v.x = clampf(clampf(v.x) * FACT);
    v.y = clampf(clampf(v.y) * FACT);
    v.z = clampf(clampf(v.z) * FACT);
    v.w = clampf(clampf(v.w) * FACT);
    return v;
}

__global__ void __launch_bounds__(256) fused_kernel(
    const float4* __restrict__ y, const float4* __restrict__ c,
    float4* __restrict__ oy, float4* __restrict__ oc)
{
    __shared__ float s_warp[8];
    __shared__ float s_mean;

    // ---- Extra duty: DC reduction on first 512 blocks (wave 1) ----
    if (blockIdx.x < N_RED_BLK) {
        int idx = blockIdx.x * 256 + threadIdx.x;            // 0 .. 131071
        int ch  = idx >> 16;                                 // constant per block
        // DC coeff idx lives at c-element idx*64 == float4 idx*16, component .x
        float v = clampf(c[(long long)idx * 16].x);

        #pragma unroll
        for (int off = 16; off > 0; off >>= 1)
            v += __shfl_down_sync(0xffffffffu, v, off);
        if ((threadIdx.x & 31) == 0) s_warp[threadIdx.x >> 5] = v;
        __syncthreads();
        if (threadIdx.x < 8) {
            float w = s_warp[threadIdx.x];
            #pragma unroll
            for (int off = 4; off > 0; off >>= 1)
                w += __shfl_down_sync(0xffu, w, off);
            if (threadIdx.x == 0) {
                atomicAdd(&g_dc_sum[ch], w);
                __threadfence();
                atomicAdd(&g_red_cnt, 1);
            }
        }
    }

    // Block owns 512 consecutive float4s; each thread takes tid and tid+256.
    long long base = (long long)blockIdx.x * 512;
    long long i0 = base + threadIdx.x;
    long long i1 = i0 + 256;

    if (blockIdx.x < 8192) {
        // ---- pure-y block ----
        float4 a = y[i0];
        float4 b = y[i1];
        oy[i0] = y_op(a);
        oy[i1] = y_op(b);
    } else {
        // ---- pure-c block ----
        long long j0 = i0 - NY4;                  // 0 .. NC4-1
        long long j1 = i1 - NY4;
        int ch = (int)(j0 >> 20);                 // constant per block

        // One thread waits (reduction finished many waves ago) and reads the
        // mean exactly once; everyone else gets it through shared memory.
        if (threadIdx.x == 0) {
            while (*((volatile int*)&g_red_cnt) != N_RED_BLK) { }
            s_mean = (*((volatile float*)&g_dc_sum[ch])) * INV_CNT;
        }

        float4 a = c[j0];                         // loads overlap the wait
        float4 b = c[j1];
        __syncthreads();
        float blend = (1.0f - FACT) * s_mean;

        a.x = clampf(a.x) * FACT;
        a.y = clampf(a.y) * FACT;
        a.z = clampf(a.z) * FACT;
        a.w = clampf(a.w) * FACT;
        if ((j0 & 15) == 0) a.x += blend;         // elem j0*4 is a DC coeff
        a.x = clampf(a.x); a.y = clampf(a.y); a.z = clampf(a.z); a.w = clampf(a.w);
        oc[j0] = a;

        b.x = clampf(b.x) * FACT;
        b.y = clampf(b.y) * FACT;
        b.z = clampf(b.z) * FACT;
        b.w = clampf(b.w) * FACT;
        if ((j1 & 15) == 0) b.x += blend;
        b.x = clampf(b.x); b.y = clampf(b.y); b.z = clampf(b.z); b.w = clampf(b.w);
        oc[j1] = b;

        // ---- reset globals for next graph replay (last finished c-block) ----
        __syncthreads();
        if (threadIdx.x == 0) {
            int old = atomicAdd(&g_c_done, 1);
            if (old == N_C_BLK - 1) {
                *((volatile float*)&g_dc_sum[0]) = 0.0f;
                *((volatile float*)&g_dc_sum[1]) = 0.0f;
                *((volatile int*)&g_red_cnt)     = 0;
                *((volatile int*)&g_c_done)      = 0;
                __threadfence();
            }
        }
    }
}

extern "C" void kernel_launch(void* const* d_in, const int* in_sizes, int n_in,
                              void* d_out, int out_size) {
    const float4* y = (const float4*)d_in[0];
    const float4* c = (const float4*)d_in[1];
    float4* oy = (float4*)d_out;
    float4* oc = (float4*)((float*)d_out + NY4 * 4);

    unsigned grid = (unsigned)((NY4 + NC4) / 512);   // 12,288 blocks
    fused_kernel<<<grid, 256>>>(y, c, oy, oc);
}

// round 5
// speedup vs baseline: 1.4458x; 1.0383x over previous
#include <cuda_runtime.h>

// Problem geometry (fixed by the dataset):
//   y: [1,512,512,8,8] f32 = 16,777,216 elems
//   c: [2,256,256,8,8] f32 =  8,388,608 elems (2 channels x 4,194,304)
// Output: y then c concatenated, 25,165,824 f32.
//
// Single fused launch, 6,144 blocks x 256 threads, 4 float4 per thread
// (each block owns 1024 consecutive float4s):
//   blocks [0, 512)      : extra duty — DC reduction (one clamped DC/thread),
//                          atomicAdd into g_dc_sum, bump g_red_cnt.
//   blocks [0, 4096)     : y elementwise (NY4/1024 == 4096 exactly).
//   blocks [4096, 6144)  : c elementwise. Thread 0 polls g_red_cnt (reducers
//                          finished waves earlier), reads the mean once,
//                          broadcasts via shared memory.
//   Bulk stream uses __ldcs/__stcs (touch-once data; keep L2 for the DC
//   lines that the reducers prefetch for the c-blocks).
//   Last finished c-block resets globals for the next graph replay.

#define CMIN  (-1024.0f)
#define CMAX  (1016.0f)
#define FACT  (1.9f)

static const int   NY4       = 4194304;    // y float4 count
static const int   NC4       = 2097152;    // c float4 count
static const int   N_Y_BLK   = 4096;       // pure-y blocks
static const int   N_RED_BLK = 512;        // reducer blocks (256 DC each)
static const int   N_C_BLK   = 2048;       // c blocks
static const float INV_CNT   = 1.0f / 65536.0f;

__device__ float g_dc_sum[2];
__device__ int   g_red_cnt;
__device__ int   g_c_done;

__device__ __forceinline__ float clampf(float v) {
    return fminf(fmaxf(v, CMIN), CMAX);
}

__device__ __forceinline__ float4 y_op(float4 v) {
    v.x = clampf(clampf(v.x) * FACT);
    v.y = clampf(clampf(v.y) * FACT);
    v.z = clampf(clampf(v.z) * FACT);
    v.w = clampf(clampf(v.w) * FACT);
    return v;
}

__device__ __forceinline__ float4 c_op(float4 v, int j, float blend) {
    v.x = clampf(v.x) * FACT;
    v.y = clampf(v.y) * FACT;
    v.z = clampf(v.z) * FACT;
    v.w = clampf(v.w) * FACT;
    if ((j & 15) == 0) v.x += blend;   // elem j*4 is a DC coeff (idx%64==0)
    v.x = clampf(v.x);
    v.y = clampf(v.y);
    v.z = clampf(v.z);
    v.w = clampf(v.w);
    return v;
}

__global__ void __launch_bounds__(256) fused_kernel(
    const float4* __restrict__ y, const float4* __restrict__ c,
    float4* __restrict__ oy, float4* __restrict__ oc)
{
    __shared__ float s_warp[8];
    __shared__ float s_mean;

    // ---- Extra duty: DC reduction on first 512 blocks (wave 1) ----
    if (blockIdx.x < N_RED_BLK) {
        int idx = blockIdx.x * 256 + threadIdx.x;   // 0 .. 131071
        int ch  = idx >> 16;                        // constant per block
        // DC coeff idx lives at c-element idx*64 == float4 idx*16, comp .x
        // Default (caching) load: c-blocks re-read these lines later.
        float v = clampf(c[idx * 16].x);

        #pragma unroll
        for (int off = 16; off > 0; off >>= 1)
            v += __shfl_down_sync(0xffffffffu, v, off);
        if ((threadIdx.x & 31) == 0) s_warp[threadIdx.x >> 5] = v;
        __syncthreads();
        if (threadIdx.x < 8) {
            float w = s_warp[threadIdx.x];
            #pragma unroll
            for (int off = 4; off > 0; off >>= 1)
                w += __shfl_down_sync(0xffu, w, off);
            if (threadIdx.x == 0) {
                atomicAdd(&g_dc_sum[ch], w);
                __threadfence();
                atomicAdd(&g_red_cnt, 1);
            }
        }
    }

    // Block owns 1024 consecutive float4s; thread takes tid + {0,256,512,768}.
    int i0 = blockIdx.x * 1024 + threadIdx.x;

    if (blockIdx.x < N_Y_BLK) {
        // ---- pure-y block: 4 front-batched streaming loads ----
        float4 a = __ldcs(&y[i0]);
        float4 b = __ldcs(&y[i0 + 256]);
        float4 d = __ldcs(&y[i0 + 512]);
        float4 e = __ldcs(&y[i0 + 768]);
        __stcs(&oy[i0],       y_op(a));
        __stcs(&oy[i0 + 256], y_op(b));
        __stcs(&oy[i0 + 512], y_op(d));
        __stcs(&oy[i0 + 768], y_op(e));
    } else {
        // ---- pure-c block ----
        int j0 = i0 - NY4;                   // 0 .. NC4-1
        int ch = j0 >> 20;                   // constant per block (1M-aligned)

        // One thread waits (reduction finished waves ago) and reads the mean
        // exactly once; everyone else gets it through shared memory.
        if (threadIdx.x == 0) {
            while (*((volatile int*)&g_red_cnt) != N_RED_BLK) { }
            s_mean = (*((volatile float*)&g_dc_sum[ch])) * INV_CNT;
        }

        float4 a = __ldcs(&c[j0]);           // loads overlap the wait
        float4 b = __ldcs(&c[j0 + 256]);
        float4 d = __ldcs(&c[j0 + 512]);
        float4 e = __ldcs(&c[j0 + 768]);
        __syncthreads();
        float blend = (1.0f - FACT) * s_mean;

        __stcs(&oc[j0],       c_op(a, j0,       blend));
        __stcs(&oc[j0 + 256], c_op(b, j0 + 256, blend));
        __stcs(&oc[j0 + 512], c_op(d, j0 + 512, blend));
        __stcs(&oc[j0 + 768], c_op(e, j0 + 768, blend));

        // ---- reset globals for next graph replay (last finished c-block) ----
        __syncthreads();
        if (threadIdx.x == 0) {
            int old = atomicAdd(&g_c_done, 1);
            if (old == N_C_BLK - 1) {
                *((volatile float*)&g_dc_sum[0]) = 0.0f;
                *((volatile float*)&g_dc_sum[1]) = 0.0f;
                *((volatile int*)&g_red_cnt)     = 0;
                *((volatile int*)&g_c_done)      = 0;
                __threadfence();
            }
        }
    }
}

extern "C" void kernel_launch(void* const* d_in, const int* in_sizes, int n_in,
                              void* d_out, int out_size) {
    const float4* y = (const float4*)d_in[0];
    const float4* c = (const float4*)d_in[1];
    float4* oy = (float4*)d_out;
    float4* oc = (float4*)d_out + NY4;

    unsigned grid = (unsigned)(N_Y_BLK + N_C_BLK);   // 6,144 blocks
    fused_kernel<<<grid, 256>>>(y, c, oy, oc);
}